// round 14
// baseline (speedup 1.0000x reference)
#include <cuda_runtime.h>
#include <math.h>

#define LSEQ 262144
#define NMODE 64
#define TCH 128
#define NCHUNK (LSEQ / TCH)   // 2048
#define WPB 8
#define BTH 256
#define NBLK (NCHUNK / WPB)   // 256 blocks
#define SEGCH 512             // chunks per scan segment
#define NSEG (NCHUNK / SEGCH) // 4

typedef unsigned long long u64;

// intermediates [mode][chunk]
__device__ __align__(16) float2 g_P[NMODE * NCHUNK];
__device__ __align__(16) float2 g_C[NMODE * NCHUNK];   // within-seg exclusive carries
__device__ __align__(16) float2 g_T[NMODE * NSEG];     // segment inclusive totals
// grid barrier counters (monotonic across graph replays)
__device__ u64 g_bar1 = 0, g_bar2 = 0;

// ---- packed f32x2 helpers ----
__device__ __forceinline__ u64 pk2(float lo, float hi) {
    u64 r; asm("mov.b64 %0, {%1,%2};" : "=l"(r) : "f"(lo), "f"(hi)); return r;
}
__device__ __forceinline__ void upk2(u64 v, float& lo, float& hi) {
    asm("mov.b64 {%0,%1}, %2;" : "=f"(lo), "=f"(hi) : "l"(v));
}
__device__ __forceinline__ u64 fma2(u64 a, u64 b, u64 c) {
    u64 d; asm("fma.rn.f32x2 %0, %1, %2, %3;" : "=l"(d) : "l"(a), "l"(b), "l"(c)); return d;
}
__device__ __forceinline__ u64 mul2(u64 a, u64 b) {
    u64 d; asm("mul.rn.f32x2 %0, %1, %2;" : "=l"(d) : "l"(a), "l"(b)); return d;
}

// Replay-safe grid barrier: each launch adds exactly NBLK arrivals.
__device__ __forceinline__ void grid_barrier(u64* ctr) {
    __syncthreads();
    if (threadIdx.x == 0) {
        __threadfence();
        u64 old = atomicAdd(ctr, 1ULL);
        u64 target = (old / NBLK + 1) * (u64)NBLK;
        while (*(volatile u64*)ctr < target) __nanosleep(32);
        __threadfence();
    }
    __syncthreads();
}

// complex binary pow (scalar), k >= 0
__device__ __forceinline__ void cpowk(float br, float bi, int k, float& rr, float& ri) {
    rr = 1.f; ri = 0.f;
    while (k) {
        if (k & 1) { float t = rr * br - ri * bi; ri = rr * bi + ri * br; rr = t; }
        float t2 = br * br - bi * bi; bi = 2.f * br * bi; br = t2;
        k >>= 1;
    }
}

__global__ __launch_bounds__(BTH) void fused_kernel(
    const float* __restrict__ u, const float* __restrict__ A_re,
    const float* __restrict__ A_im, const float* __restrict__ Cin,
    const float* __restrict__ D, const float* __restrict__ log_step,
    float* __restrict__ y)
{
    __shared__ __align__(16) float su[WPB * TCH];       // 4KB, lives A->C
    __shared__ __align__(16) float2 sP[NMODE][WPB];     // 4KB (partials / carries)
    __shared__ __align__(16) float red[WPB][32 * 33];   // 33.8KB transpose-reduce
    __shared__ float sre[BTH], sim_[BTH];               // 2KB scan

    int tid = threadIdx.x, warp = tid >> 5, lane = tid & 31;
    int blk = blockIdx.x;
    int base = blk * (WPB * TCH);

    // ---- per-lane constants for modes (lane, lane+32) ----
    float dt = expf(__ldg(log_step));
    float zr0, zi0, zr1, zi1, cfr0, cfi0, cfr1, cfi1;
    {
        int m = lane;
        float ar = __ldg(&A_re[m]), ai = __ldg(&A_im[m]);
        float e = expf(dt * ar);
        zr0 = e * cosf(dt * ai); zi0 = e * sinf(dt * ai);
        float nr = zr0 - 1.f, ni = zi0;
        float inv = 1.f / (ar * ar + ai * ai);
        float tre = (nr * ar + ni * ai) * inv, tim = (ni * ar - nr * ai) * inv;
        float cr = __ldg(&Cin[2 * m]), ci = __ldg(&Cin[2 * m + 1]);
        cfr0 = cr * tre - ci * tim; cfi0 = cr * tim + ci * tre;
    }
    {
        int m = lane + 32;
        float ar = __ldg(&A_re[m]), ai = __ldg(&A_im[m]);
        float e = expf(dt * ar);
        zr1 = e * cosf(dt * ai); zi1 = e * sinf(dt * ai);
        float nr = zr1 - 1.f, ni = zi1;
        float inv = 1.f / (ar * ar + ai * ai);
        float tre = (nr * ar + ni * ai) * inv, tim = (ni * ar - nr * ai) * inv;
        float cr = __ldg(&Cin[2 * m]), ci = __ldg(&Cin[2 * m + 1]);
        cfr1 = cr * tre - ci * tim; cfi1 = cr * tim + ci * tre;
    }
    u64 Zr = pk2(zr0, zr1), Zi = pk2(zi0, zi1), nZi = pk2(-zi0, -zi1);
    float z2r0 = zr0 * zr0 - zi0 * zi0, z2i0 = 2.f * zr0 * zi0;
    float z2r1 = zr1 * zr1 - zi1 * zi1, z2i1 = 2.f * zr1 * zi1;
    u64 Z2r = pk2(z2r0, z2r1), Z2i = pk2(z2i0, z2i1), nZ2i = pk2(-z2i0, -z2i1);
    float z4r0 = z2r0 * z2r0 - z2i0 * z2i0, z4i0 = 2.f * z2r0 * z2i0;
    float z4r1 = z2r1 * z2r1 - z2i1 * z2i1, z4i1 = 2.f * z2r1 * z2i1;
    u64 Z4r = pk2(z4r0, z4r1), Z4i = pk2(z4i0, z4i1), nZ4i = pk2(-z4i0, -z4i1);
    u64 F = pk2(cfr0, cfr1), nFi = pk2(-cfi0, -cfi1);

    // ================= Phase A: chunk partials (zero-init recurrence) ========
    ((float4*)su)[tid] = ((const float4*)(u + base))[tid];
    __syncthreads();
    {
        u64 sr = 0, si = 0;
        const float4* uw = (const float4*)&su[warp * TCH];
#pragma unroll
        for (int i = 0; i < TCH / 4; i++) {
            float4 uu = uw[i];
            u64 u1p = pk2(uu.x, uu.x), u2p = pk2(uu.y, uu.y);
            u64 u3p = pk2(uu.z, uu.z), u4p = pk2(uu.w, uu.w);
            u64 t1r = fma2(Zr, u1p, u2p), t1i = mul2(Zi, u1p);
            u64 t2r = fma2(Zr, u3p, u4p), t2i = mul2(Zi, u3p);
            u64 br = fma2(Z2r, t1r, fma2(nZ2i, t1i, t2r));
            u64 bi = fma2(Z2i, t1r, fma2(Z2r, t1i, t2i));
            u64 nr = fma2(Z4r, sr, fma2(nZ4i, si, br));
            u64 ni = fma2(Z4i, sr, fma2(Z4r, si, bi));
            sr = nr; si = ni;
        }
        float a, b, c, d;
        upk2(sr, a, b); upk2(si, c, d);
        sP[lane][warp]      = make_float2(a, c);
        sP[lane + 32][warp] = make_float2(b, d);
    }
    __syncthreads();
    {
        int row = tid >> 2, col = (tid & 3) * 2, c0 = blk * WPB;
        *(float4*)&g_P[row * NCHUNK + c0 + col] = *(const float4*)&sP[row][col];
    }
    grid_barrier(&g_bar1);

    // ===== Phase B: segmented scan — ALL 256 blocks busy ====================
    // block -> (mode = blk>>2, segment = blk&3 of 512 chunks), fold 2, HS-256.
    {
        int mode = blk >> 2, seg = blk & 3;
        int a0 = seg * SEGCH;
        float ar = __ldg(&A_re[mode]), ai = __ldg(&A_im[mode]);
        float e = expf(dt * ar);
        float wr = e * cosf(dt * ai), wi = e * sinf(dt * ai);
#pragma unroll
        for (int k = 0; k < 7; k++) { float t1 = wr * wr - wi * wi; wi = 2.f * wr * wi; wr = t1; } // w = z^128
        float cwr = wr * wr - wi * wi, cwi = 2.f * wr * wi;  // w^2
        int t = tid;
        float4 pp = *(const float4*)&g_P[mode * NCHUNK + a0 + 2 * t];
        float p0r = pp.x, p0i = pp.y, p1r = pp.z, p1i = pp.w;
        float vr = fmaf(wr, p0r, fmaf(-wi, p0i, p1r));
        float vi = fmaf(wi, p0r, fmaf( wr, p0i, p1i));
        sre[t] = vr; sim_[t] = vi;
        __syncthreads();
        for (int k = 1; k < BTH; k <<= 1) {
            float ore = 0.f, oim = 0.f;
            if (t >= k) { ore = sre[t - k]; oim = sim_[t - k]; }
            __syncthreads();
            vr += cwr * ore - cwi * oim;
            vi += cwr * oim + cwi * ore;
            sre[t] = vr; sim_[t] = vi;
            float nwr = cwr * cwr - cwi * cwi;
            cwi = 2.f * cwr * cwi; cwr = nwr;
            __syncthreads();
        }
        float e0r = 0.f, e0i = 0.f;
        if (t > 0) { e0r = sre[t - 1]; e0i = sim_[t - 1]; }
        float e1r = fmaf(wr, e0r, fmaf(-wi, e0i, p0r));
        float e1i = fmaf(wi, e0r, fmaf( wr, e0i, p0i));
        *(float4*)&g_C[mode * NCHUNK + a0 + 2 * t] =
            make_float4(e0r, e0i, e1r, e1i);
        if (t == BTH - 1) g_T[mode * NSEG + seg] = make_float2(vr, vi);  // seg total
    }
    grid_barrier(&g_bar2);

    // ================= Phase C: carry-seeded output recurrence ===============
    {
        int row = tid >> 2, col = (tid & 3) * 2, c0 = blk * WPB;
        *(float4*)&sP[row][col] = *(const float4*)&g_C[row * NCHUNK + c0 + col];
    }
    __syncthreads();
    {
        // ---- combine segment carry: carry = e + w^k * S_excl ----
        int seg = blk >> 6;                       // 64 blocks per segment
        int kofs = (blk & 63) * WPB + warp;       // chunk offset within segment
        // per-mode w = z^128 (7 squarings from z)
        float w0r = zr0, w0i = zi0, w1r = zr1, w1i = zi1;
#pragma unroll
        for (int k = 0; k < 7; k++) {
            float t0 = w0r * w0r - w0i * w0i; w0i = 2.f * w0r * w0i; w0r = t0;
            float t1 = w1r * w1r - w1i * w1i; w1i = 2.f * w1r * w1i; w1r = t1;
        }
        // S_excl = sum_{t<seg} w512^(seg-1-t) * T[t]
        float S0r = 0.f, S0i = 0.f, S1r = 0.f, S1i = 0.f;
        if (seg > 0) {
            // w512 = w^512 (9 squarings)
            float a0r = w0r, a0i = w0i, a1r = w1r, a1i = w1i;
#pragma unroll
            for (int k = 0; k < 9; k++) {
                float t0 = a0r * a0r - a0i * a0i; a0i = 2.f * a0r * a0i; a0r = t0;
                float t1 = a1r * a1r - a1i * a1i; a1i = 2.f * a1r * a1i; a1r = t1;
            }
            for (int t = 0; t < seg; t++) {    // Horner over seg totals
                float2 T0 = g_T[lane * NSEG + t];
                float2 T1 = g_T[(lane + 32) * NSEG + t];
                float n0r = S0r * a0r - S0i * a0i + T0.x;
                float n0i = S0r * a0i + S0i * a0r + T0.y;
                float n1r = S1r * a1r - S1i * a1i + T1.x;
                float n1i = S1r * a1i + S1i * a1r + T1.y;
                S0r = n0r; S0i = n0i; S1r = n1r; S1i = n1i;
            }
            // multiply by w^kofs and fold into e below via pw
        }
        float pw0r, pw0i, pw1r, pw1i;
        cpowk(w0r, w0i, kofs, pw0r, pw0i);
        cpowk(w1r, w1i, kofs, pw1r, pw1i);
        float2 eA = sP[lane][warp], eB = sP[lane + 32][warp];
        float c0r = eA.x + pw0r * S0r - pw0i * S0i;
        float c0i = eA.y + pw0r * S0i + pw0i * S0r;
        float c1r = eB.x + pw1r * S1r - pw1i * S1i;
        float c1i = eB.y + pw1r * S1i + pw1i * S1r;
        u64 sr = pk2(c0r, c1r), si = pk2(c0i, c1i);

        float Dv = __ldg(D);
        float* rw = &red[warp][0];
        int gbase = base + warp * TCH;
#pragma unroll
        for (int tile = 0; tile < TCH / 32; tile++) {
            const float4* uw = (const float4*)&su[warp * TCH + tile * 32];
#pragma unroll
            for (int i = 0; i < 32; i += 4) {
                float4 uu = uw[i >> 2];
                u64 u1p = pk2(uu.x, uu.x), u2p = pk2(uu.y, uu.y);
                u64 u3p = pk2(uu.z, uu.z), u4p = pk2(uu.w, uu.w);
                u64 t1r = fma2(Zr, u1p, u2p), t1i = mul2(Zi, u1p);
                u64 t2r = fma2(Zr, u3p, u4p), t2i = mul2(Zi, u3p);
                u64 s1r = fma2(Zr, sr, fma2(nZi, si, u1p));
                u64 s1i = fma2(Zi, sr, mul2(Zr, si));
                u64 s2r = fma2(Z2r, sr, fma2(nZ2i, si, t1r));
                u64 s2i = fma2(Z2i, sr, fma2(Z2r, si, t1i));
                u64 s3r = fma2(Zr, s2r, fma2(nZi, s2i, u3p));
                u64 s3i = fma2(Zi, s2r, mul2(Zr, s2i));
                u64 s4r = fma2(Z2r, s2r, fma2(nZ2i, s2i, t2r));
                u64 s4i = fma2(Z2i, s2r, fma2(Z2r, s2i, t2i));
                sr = s4r; si = s4i;
                u64 cp1 = fma2(F, s1r, mul2(nFi, s1i));
                u64 cp2 = fma2(F, s2r, mul2(nFi, s2i));
                u64 cp3 = fma2(F, s3r, mul2(nFi, s3i));
                u64 cp4 = fma2(F, s4r, mul2(nFi, s4i));
                float x0, x1, y0, y1, w0, w1, v0, v1;
                upk2(cp1, x0, x1); upk2(cp2, y0, y1);
                upk2(cp3, w0, w1); upk2(cp4, v0, v1);
                // pitch 33: STS.32 bank = lane + i (conflict-free)
                rw[lane * 33 + i]     = x0 + x1;
                rw[lane * 33 + i + 1] = y0 + y1;
                rw[lane * 33 + i + 2] = w0 + w1;
                rw[lane * 33 + i + 3] = v0 + v1;
            }
            __syncwarp();
            float acc0 = 0.f, acc1 = 0.f, acc2 = 0.f, acc3 = 0.f;
#pragma unroll
            for (int l = 0; l < 32; l += 4) {
                acc0 += rw[(l + 0) * 33 + lane];
                acc1 += rw[(l + 1) * 33 + lane];
                acc2 += rw[(l + 2) * 33 + lane];
                acc3 += rw[(l + 3) * 33 + lane];
            }
            float uv = su[warp * TCH + tile * 32 + lane];
            y[gbase + tile * 32 + lane] = fmaf(Dv, uv, (acc0 + acc1) + (acc2 + acc3));
            __syncwarp();
        }
    }
}

extern "C" void kernel_launch(void* const* d_in, const int* in_sizes, int n_in,
                              void* d_out, int out_size) {
    const float* u        = (const float*)d_in[0];
    const float* A_re     = (const float*)d_in[1];
    const float* A_im     = (const float*)d_in[2];
    const float* C        = (const float*)d_in[3];
    const float* D        = (const float*)d_in[4];
    const float* log_step = (const float*)d_in[5];
    float* y = (float*)d_out;

    static int once = 0;
    if (!once) {
        cudaFuncSetAttribute(fused_kernel,
                             cudaFuncAttributePreferredSharedMemoryCarveout, 100);
        once = 1;
    }
    fused_kernel<<<NBLK, BTH>>>(u, A_re, A_im, C, D, log_step, y);
}

// round 16
// speedup vs baseline: 1.5066x; 1.5066x over previous
#include <cuda_runtime.h>
#include <math.h>

#define LSEQ 262144
#define NMODE 64
#define TCH 128
#define NCHUNK (LSEQ / TCH)   // 2048
#define WPB 8
#define BTH 256
#define NBLK (NCHUNK / WPB)   // 256 blocks

typedef unsigned long long u64;

// intermediates [mode][chunk]
__device__ __align__(16) float2 g_P[NMODE * NCHUNK];
__device__ __align__(16) float2 g_C[NMODE * NCHUNK];
// grid barrier counters (monotonic across graph replays)
__device__ u64 g_bar1 = 0, g_bar2 = 0;

// ---- packed f32x2 helpers ----
__device__ __forceinline__ u64 pk2(float lo, float hi) {
    u64 r; asm("mov.b64 %0, {%1,%2};" : "=l"(r) : "f"(lo), "f"(hi)); return r;
}
__device__ __forceinline__ void upk2(u64 v, float& lo, float& hi) {
    asm("mov.b64 {%0,%1}, %2;" : "=f"(lo), "=f"(hi) : "l"(v));
}
__device__ __forceinline__ u64 fma2(u64 a, u64 b, u64 c) {
    u64 d; asm("fma.rn.f32x2 %0, %1, %2, %3;" : "=l"(d) : "l"(a), "l"(b), "l"(c)); return d;
}
__device__ __forceinline__ u64 mul2(u64 a, u64 b) {
    u64 d; asm("mul.rn.f32x2 %0, %1, %2;" : "=l"(d) : "l"(a), "l"(b)); return d;
}

// Replay-safe grid barrier: every launch adds exactly NBLK arrivals.
__device__ __forceinline__ void grid_barrier(u64* ctr) {
    __syncthreads();
    if (threadIdx.x == 0) {
        __threadfence();
        u64 old = atomicAdd(ctr, 1ULL);
        u64 target = (old / NBLK + 1) * (u64)NBLK;
        while (*(volatile u64*)ctr < target) __nanosleep(32);
        __threadfence();
    }
    __syncthreads();
}

__global__ __launch_bounds__(BTH) void fused_kernel(
    const float* __restrict__ u, const float* __restrict__ A_re,
    const float* __restrict__ A_im, const float* __restrict__ Cin,
    const float* __restrict__ D, const float* __restrict__ log_step,
    float* __restrict__ y)
{
    __shared__ __align__(16) float su[WPB * TCH];       // 4KB, lives A->C
    __shared__ __align__(16) float2 sP[NMODE][WPB];     // 4KB (partials, then carries)
    __shared__ __align__(16) float red[WPB][32 * 34];   // ~34.8KB transpose-reduce
    __shared__ float sre[BTH], sim_[BTH];               // 2KB scan

    int tid = threadIdx.x, warp = tid >> 5, lane = tid & 31;
    int blk = blockIdx.x;
    int base = blk * (WPB * TCH);

    // ---- per-lane constants for modes (lane, lane+32) ----
    float dt = expf(__ldg(log_step));
    float zr0, zi0, zr1, zi1, cfr0, cfi0, cfr1, cfi1;
    {
        int m = lane;
        float ar = __ldg(&A_re[m]), ai = __ldg(&A_im[m]);
        float e = expf(dt * ar);
        zr0 = e * cosf(dt * ai); zi0 = e * sinf(dt * ai);
        float nr = zr0 - 1.f, ni = zi0;
        float inv = 1.f / (ar * ar + ai * ai);
        float tre = (nr * ar + ni * ai) * inv, tim = (ni * ar - nr * ai) * inv;
        float cr = __ldg(&Cin[2 * m]), ci = __ldg(&Cin[2 * m + 1]);
        cfr0 = cr * tre - ci * tim; cfi0 = cr * tim + ci * tre;
    }
    {
        int m = lane + 32;
        float ar = __ldg(&A_re[m]), ai = __ldg(&A_im[m]);
        float e = expf(dt * ar);
        zr1 = e * cosf(dt * ai); zi1 = e * sinf(dt * ai);
        float nr = zr1 - 1.f, ni = zi1;
        float inv = 1.f / (ar * ar + ai * ai);
        float tre = (nr * ar + ni * ai) * inv, tim = (ni * ar - nr * ai) * inv;
        float cr = __ldg(&Cin[2 * m]), ci = __ldg(&Cin[2 * m + 1]);
        cfr1 = cr * tre - ci * tim; cfi1 = cr * tim + ci * tre;
    }
    u64 Zr = pk2(zr0, zr1), Zi = pk2(zi0, zi1);
    float z2r0 = zr0 * zr0 - zi0 * zi0, z2i0 = 2.f * zr0 * zi0;
    float z2r1 = zr1 * zr1 - zi1 * zi1, z2i1 = 2.f * zr1 * zi1;
    u64 Z2r = pk2(z2r0, z2r1), Z2i = pk2(z2i0, z2i1), nZ2i = pk2(-z2i0, -z2i1);
    float z4r0 = z2r0 * z2r0 - z2i0 * z2i0, z4i0 = 2.f * z2r0 * z2i0;
    float z4r1 = z2r1 * z2r1 - z2i1 * z2i1, z4i1 = 2.f * z2r1 * z2i1;
    u64 Z4r = pk2(z4r0, z4r1), Z4i = pk2(z4i0, z4i1), nZ4i = pk2(-z4i0, -z4i1);

    // ================= Phase A: chunk partials (zero-init recurrence) ========
    ((float4*)su)[tid] = ((const float4*)(u + base))[tid];
    __syncthreads();
    {
        u64 sr = 0, si = 0;
        const float4* uw = (const float4*)&su[warp * TCH];
#pragma unroll
        for (int i = 0; i < TCH / 4; i++) {
            float4 uu = uw[i];
            u64 u1p = pk2(uu.x, uu.x), u2p = pk2(uu.y, uu.y);
            u64 u3p = pk2(uu.z, uu.z), u4p = pk2(uu.w, uu.w);
            u64 t1r = fma2(Zr, u1p, u2p), t1i = mul2(Zi, u1p);
            u64 t2r = fma2(Zr, u3p, u4p), t2i = mul2(Zi, u3p);
            u64 br = fma2(Z2r, t1r, fma2(nZ2i, t1i, t2r));
            u64 bi = fma2(Z2i, t1r, fma2(Z2r, t1i, t2i));
            u64 nr = fma2(Z4r, sr, fma2(nZ4i, si, br));
            u64 ni = fma2(Z4i, sr, fma2(Z4r, si, bi));
            sr = nr; si = ni;
        }
        float a, b, c, d;
        upk2(sr, a, b); upk2(si, c, d);
        sP[lane][warp]      = make_float2(a, c);
        sP[lane + 32][warp] = make_float2(b, d);
    }
    __syncthreads();
    {
        int row = tid >> 2, col = (tid & 3) * 2, c0 = blk * WPB;
        *(float4*)&g_P[row * NCHUNK + c0 + col] = *(const float4*)&sP[row][col];
    }
    grid_barrier(&g_bar1);

    // ================= Phase B: per-mode scan (blocks 0..63) =================
    if (blk < NMODE) {
        int mode = blk;
        float ar = __ldg(&A_re[mode]), ai = __ldg(&A_im[mode]);
        float e = expf(dt * ar);
        float wr = e * cosf(dt * ai), wi = e * sinf(dt * ai);
#pragma unroll
        for (int k = 0; k < 7; k++) { float t1 = wr * wr - wi * wi; wi = 2.f * wr * wi; wr = t1; }  // z^128
        float Wr = wr, Wi = wi;
#pragma unroll
        for (int k = 0; k < 3; k++) { float t1 = Wr * Wr - Wi * Wi; Wi = 2.f * Wr * Wi; Wr = t1; }  // w^8
        int t = tid;
        float2 p[8];
        const float2* P = &g_P[mode * NCHUNK + 8 * t];
#pragma unroll
        for (int q = 0; q < 4; q++) {
            float4 a = *(const float4*)&P[2 * q];
            p[2 * q]     = make_float2(a.x, a.y);
            p[2 * q + 1] = make_float2(a.z, a.w);
        }
        float vr = p[0].x, vi = p[0].y;
#pragma unroll
        for (int j = 1; j < 8; j++) {
            float nr2 = fmaf(wr, vr, fmaf(-wi, vi, p[j].x));
            float ni2 = fmaf(wi, vr, fmaf( wr, vi, p[j].y));
            vr = nr2; vi = ni2;
        }
        sre[t] = vr; sim_[t] = vi;
        float cwr = Wr, cwi = Wi;
        __syncthreads();
        for (int k = 1; k < BTH; k <<= 1) {
            float ore = 0.f, oim = 0.f;
            if (t >= k) { ore = sre[t - k]; oim = sim_[t - k]; }
            __syncthreads();
            vr += cwr * ore - cwi * oim;
            vi += cwr * oim + cwi * ore;
            sre[t] = vr; sim_[t] = vi;
            float nwr = cwr * cwr - cwi * cwi;
            cwi = 2.f * cwr * cwi; cwr = nwr;
            __syncthreads();
        }
        float er = 0.f, ei = 0.f;
        if (t > 0) { er = sre[t - 1]; ei = sim_[t - 1]; }
        float2 ec[8];
        ec[0] = make_float2(er, ei);
#pragma unroll
        for (int j = 1; j < 8; j++) {
            float nr2 = fmaf(wr, er, fmaf(-wi, ei, p[j - 1].x));
            float ni2 = fmaf(wi, er, fmaf( wr, ei, p[j - 1].y));
            er = nr2; ei = ni2;
            ec[j] = make_float2(er, ei);
        }
        float2* Cp = &g_C[mode * NCHUNK + 8 * t];
#pragma unroll
        for (int q = 0; q < 4; q++)
            *(float4*)&Cp[2 * q] = make_float4(ec[2 * q].x, ec[2 * q].y,
                                               ec[2 * q + 1].x, ec[2 * q + 1].y);
    }
    grid_barrier(&g_bar2);

    // ===== Phase C: real 2nd-order recurrence  r = a r1 + b r2 + alpha u + beta u_prev
    {
        int row = tid >> 2, col = (tid & 3) * 2, c0 = blk * WPB;
        *(float4*)&sP[row][col] = *(const float4*)&g_C[row * NCHUNK + c0 + col];
    }
    __syncthreads();
    {
        // per-mode real coefficients
        float a0 = 2.f * zr0, b0 = -(zr0 * zr0 + zi0 * zi0);
        float a1 = 2.f * zr1, b1 = -(zr1 * zr1 + zi1 * zi1);
        float al0 = cfr0, be0 = -(cfr0 * zr0 + cfi0 * zi0);
        float al1 = cfr1, be1 = -(cfr1 * zr1 + cfi1 * zi1);
        u64 ap  = pk2(a0, a1),  bp  = pk2(b0, b1);
        u64 alp = pk2(al0, al1), bep = pk2(be0, be1);
        u64 A2p = pk2(a0 * a0 + b0, a1 * a1 + b1);   // a^2 + b
        u64 B2p = pk2(a0 * b0, a1 * b1);             // a*b

        // seeds from complex carry S: r1 = Re(cf*S); r2 = Re(cf*(S-uprev)/z)
        int gch = blk * WPB + warp;
        float uprev = 0.f;
        if (gch > 0) uprev = __ldg(&u[gch * TCH - 1]);
        float2 SA = sP[lane][warp], SB = sP[lane + 32][warp];
        float r1s0 = cfr0 * SA.x - cfi0 * SA.y;
        float r1s1 = cfr1 * SB.x - cfi1 * SB.y;
        float iv0 = 1.f / (zr0 * zr0 + zi0 * zi0);
        float iv1 = 1.f / (zr1 * zr1 + zi1 * zi1);
        float d0r = SA.x - uprev, d0i = SA.y;
        float d1r = SB.x - uprev, d1i = SB.y;
        float S20r = (d0r * zr0 + d0i * zi0) * iv0;   // (S-up)*conj(z)/|z|^2
        float S20i = (d0i * zr0 - d0r * zi0) * iv0;
        float S21r = (d1r * zr1 + d1i * zi1) * iv1;
        float S21i = (d1i * zr1 - d1r * zi1) * iv1;
        float r2s0 = cfr0 * S20r - cfi0 * S20i;
        float r2s1 = cfr1 * S21r - cfi1 * S21i;
        u64 r1 = pk2(r1s0, r1s1), r2 = pk2(r2s0, r2s1);
        u64 ulm1 = pk2(uprev, uprev);

        float Dv = __ldg(D);
        float* rw = &red[warp][0];
        int gbase = base + warp * TCH;
#pragma unroll
        for (int tile = 0; tile < TCH / 32; tile++) {
#pragma unroll
            for (int i = 0; i < 32; i += 2) {
                float2 uu = *(const float2*)&su[warp * TCH + tile * 32 + i];
                u64 ul  = pk2(uu.x, uu.x);
                u64 ul2 = pk2(uu.y, uu.y);
                u64 t1 = fma2(alp, ul,  mul2(bep, ulm1));   // t[l]   (off chain)
                u64 t2 = fma2(alp, ul2, mul2(bep, ul));     // t[l+1] (off chain)
                u64 T2 = fma2(ap, t1, t2);                  // off chain
                u64 rA = fma2(ap,  r1, fma2(bp,  r2, t1));  // r[l]
                u64 rB = fma2(A2p, r1, fma2(B2p, r2, T2));  // r[l+1] (chain: 2/2elem)
                r2 = rA; r1 = rB; ulm1 = ul2;
                float x0, x1, y0, y1;
                upk2(rA, x0, x1); upk2(rB, y0, y1);
                *(float2*)&rw[lane * 34 + i] = make_float2(x0 + x1, y0 + y1);
            }
            __syncwarp();
            float acc0 = 0.f, acc1 = 0.f, acc2 = 0.f, acc3 = 0.f;
#pragma unroll
            for (int l = 0; l < 32; l += 4) {
                acc0 += rw[(l + 0) * 34 + lane];
                acc1 += rw[(l + 1) * 34 + lane];
                acc2 += rw[(l + 2) * 34 + lane];
                acc3 += rw[(l + 3) * 34 + lane];
            }
            float uv = su[warp * TCH + tile * 32 + lane];
            y[gbase + tile * 32 + lane] = fmaf(Dv, uv, (acc0 + acc1) + (acc2 + acc3));
            __syncwarp();
        }
    }
}

extern "C" void kernel_launch(void* const* d_in, const int* in_sizes, int n_in,
                              void* d_out, int out_size) {
    const float* u        = (const float*)d_in[0];
    const float* A_re     = (const float*)d_in[1];
    const float* A_im     = (const float*)d_in[2];
    const float* C        = (const float*)d_in[3];
    const float* D        = (const float*)d_in[4];
    const float* log_step = (const float*)d_in[5];
    float* y = (float*)d_out;

    static int once = 0;
    if (!once) {
        cudaFuncSetAttribute(fused_kernel,
                             cudaFuncAttributePreferredSharedMemoryCarveout, 100);
        once = 1;
    }
    fused_kernel<<<NBLK, BTH>>>(u, A_re, A_im, C, D, log_step, y);
}